// round 15
// baseline (speedup 1.0000x reference)
#include <cuda_runtime.h>
#include <cuda_fp16.h>
#include <mma.h>

using namespace nvcuda;

#define NU 100000
#define NP 50000
#define NE 2000000
#define NLAB 500000
#define HD 64

// ---------------- device scratch ----------------
__device__ int g_deg_p[NP];
__device__ int g_deg_u[NU];
__device__ int g_off_p[NP];
__device__ int g_off_u[NU];
__device__ int g_cur_p[NP];
__device__ int g_cur_u[NU];
__device__ __align__(16) int g_csr_src[NE];
__device__ __align__(16) int g_csr_dst[NE];
__device__ __align__(16) __half g_tu[NU * HD];
__device__ __align__(16) __half g_tp[NP * HD];
__device__ __align__(16) __half g_tu2[NU * HD];
__device__ __align__(16) __half g_tp2[NP * HD];
__device__ __align__(16) __half g_cu[NU * HD];
__device__ __align__(16) __half g_cp[NP * HD];
__device__ __align__(16) float g_hu[NU * HD];
__device__ __align__(16) float g_hp[NP * HD];
__device__ __align__(16) float g_hu2[NU * HD];
__device__ __align__(16) float g_hp2[NP * HD];
__device__ int g_bsum_p[128];
__device__ int g_bsum_u[128];

// ---------------- CSR build (per side) ----------------
__global__ void k_zero_side(int* __restrict__ deg, int* __restrict__ cur, int n) {
    int i = blockIdx.x * blockDim.x + threadIdx.x;
    if (i < n) { deg[i] = 0; cur[i] = 0; }
}

__global__ void k_degree_side(const int* __restrict__ key, int* __restrict__ deg) {
    int i = blockIdx.x * blockDim.x + threadIdx.x;
    if (i < NE) atomicAdd(&deg[key[i]], 1);
}

__global__ void k_scan1(const int* __restrict__ deg, int n, int* __restrict__ out, int* __restrict__ bsums) {
    __shared__ int s[1024];
    int tid = threadIdx.x;
    int i = blockIdx.x * 1024 + tid;
    int v = (i < n) ? deg[i] : 0;
    s[tid] = v;
    __syncthreads();
    #pragma unroll
    for (int o = 1; o < 1024; o <<= 1) {
        int t = 0;
        if (tid >= o) t = s[tid - o];
        __syncthreads();
        s[tid] += t;
        __syncthreads();
    }
    if (i < n) out[i] = s[tid] - v;
    if (tid == 1023) bsums[blockIdx.x] = s[1023];
}

__global__ void k_scan2(int* __restrict__ bsums, int nb) {
    __shared__ int s[1024];
    int tid = threadIdx.x;
    int v = (tid < nb) ? bsums[tid] : 0;
    s[tid] = v;
    __syncthreads();
    #pragma unroll
    for (int o = 1; o < 1024; o <<= 1) {
        int t = 0;
        if (tid >= o) t = s[tid - o];
        __syncthreads();
        s[tid] += t;
        __syncthreads();
    }
    if (tid < nb) bsums[tid] = s[tid] - v;
}

__global__ void k_scan3(int* __restrict__ out, int n, const int* __restrict__ bsums) {
    int i = blockIdx.x * 1024 + threadIdx.x;
    if (i < n) out[i] += bsums[blockIdx.x];
}

__global__ void k_fill_side(const int* __restrict__ key, const int* __restrict__ val,
                            const int* __restrict__ off, int* __restrict__ cur,
                            int* __restrict__ csr) {
    int i = blockIdx.x * blockDim.x + threadIdx.x;
    if (i < NE) {
        int k = key[i];
        int slot = atomicAdd(&cur[k], 1);
        csr[off[k] + slot] = val[i];
    }
}

// ---------------- tensor-core dual GEMM: outa(h16)=x@Wa, outb(f32)=x@Wb+bb ----------------
// 32 rows/block, 8 warps -> 2x4 wmma 16x16 tiles, dual accumulators share A-frag.
template <int DIN>
__global__ __launch_bounds__(256) void k_gemm2_tc(const float* __restrict__ x,
                                                  const float* __restrict__ Wa,
                                                  const float* __restrict__ Wb,
                                                  const float* __restrict__ bb,
                                                  __half* __restrict__ outa,
                                                  float* __restrict__ outb, int n) {
    extern __shared__ __align__(16) char smraw[];
    __half* WsA = (__half*)smraw;                // DIN*64 halves
    __half* WsB = WsA + DIN * 64;                // DIN*64 halves
    __half* xh  = WsB + DIN * 64;                // 32*DIN halves
    float* outA = (float*)smraw;                 // 32*64 f32 (aliases W region post-compute)
    float* outB = outA + 32 * 64;

    int tid = threadIdx.x;
    int row0 = blockIdx.x * 32;

    for (int i = tid; i < DIN * 64; i += 256) {
        WsA[i] = __float2half_rn(Wa[i]);
        WsB[i] = __float2half_rn(Wb[i]);
    }
    for (int i = tid; i < 32 * DIN; i += 256) {
        int r = i / DIN, c = i % DIN;
        int row = row0 + r;
        xh[i] = (row < n) ? __float2half_rn(x[row * DIN + c]) : __float2half_rn(0.f);
    }
    __syncthreads();

    int w = tid >> 5;
    int rt = w >> 2;      // 0..1 row tile
    int ct = w & 3;       // 0..3 col tile

    wmma::fragment<wmma::matrix_a, 16, 16, 16, __half, wmma::row_major> fa;
    wmma::fragment<wmma::matrix_b, 16, 16, 16, __half, wmma::row_major> fba, fbb;
    wmma::fragment<wmma::accumulator, 16, 16, 16, float> ca, cb;
    wmma::fill_fragment(ca, 0.f);
    wmma::fill_fragment(cb, 0.f);

    #pragma unroll
    for (int k = 0; k < DIN; k += 16) {
        wmma::load_matrix_sync(fa, xh + (rt * 16) * DIN + k, DIN);
        wmma::load_matrix_sync(fba, WsA + k * 64 + ct * 16, 64);
        wmma::load_matrix_sync(fbb, WsB + k * 64 + ct * 16, 64);
        wmma::mma_sync(ca, fa, fba, ca);
        wmma::mma_sync(cb, fa, fbb, cb);
    }

    __syncthreads();   // all compute done before aliased epilogue staging
    wmma::store_matrix_sync(outA + (rt * 16) * 64 + ct * 16, ca, 64, wmma::mem_row_major);
    wmma::store_matrix_sync(outB + (rt * 16) * 64 + ct * 16, cb, 64, wmma::mem_row_major);
    __syncthreads();

    for (int i = tid; i < 32 * 64; i += 256) {
        int r = i >> 6, c = i & 63;
        int row = row0 + r;
        if (row < n) {
            outa[(size_t)row * 64 + c] = __float2half_rn(outA[i]);
            outb[(size_t)row * 64 + c] = outB[i] + bb[c];
        }
    }
}

// ---------------- aggregation body: warp per node, 4 edges in flight ----------------
template <bool RELU, bool H16OUT>
__device__ __forceinline__ void agg_node(const __half* __restrict__ t,
                                         const int* __restrict__ csr,
                                         const int* __restrict__ off,
                                         const int* __restrict__ deg,
                                         float* __restrict__ h,
                                         __half* __restrict__ hout16,
                                         int node, int lane) {
    int start = off[node];
    int d = deg[node];
    int grp = lane >> 3;
    int l8 = lane & 7;

    float a0 = 0.f, a1 = 0.f, a2 = 0.f, a3 = 0.f;
    float a4 = 0.f, a5 = 0.f, a6 = 0.f, a7 = 0.f;
    for (int e = grp; e < d; e += 4) {
        int s = __ldg(&csr[start + e]);
        uint4 r = *(const uint4*)(t + (size_t)s * 64 + l8 * 8);
        float2 f0 = __half22float2(*(const __half2*)&r.x);
        float2 f1 = __half22float2(*(const __half2*)&r.y);
        float2 f2 = __half22float2(*(const __half2*)&r.z);
        float2 f3 = __half22float2(*(const __half2*)&r.w);
        a0 += f0.x; a1 += f0.y; a2 += f1.x; a3 += f1.y;
        a4 += f2.x; a5 += f2.y; a6 += f3.x; a7 += f3.y;
    }
    #pragma unroll
    for (int o = 16; o >= 8; o >>= 1) {
        a0 += __shfl_down_sync(0xffffffffu, a0, o);
        a1 += __shfl_down_sync(0xffffffffu, a1, o);
        a2 += __shfl_down_sync(0xffffffffu, a2, o);
        a3 += __shfl_down_sync(0xffffffffu, a3, o);
        a4 += __shfl_down_sync(0xffffffffu, a4, o);
        a5 += __shfl_down_sync(0xffffffffu, a5, o);
        a6 += __shfl_down_sync(0xffffffffu, a6, o);
        a7 += __shfl_down_sync(0xffffffffu, a7, o);
    }

    if (lane < 8) {
        float inv = 1.0f / (float)((d > 1) ? d : 1);
        size_t base = (size_t)node * 64 + l8 * 8;
        float4 s0 = *(const float4*)&h[base];
        float4 s1 = *(const float4*)&h[base + 4];
        float o0 = fmaf(a0, inv, s0.x), o1 = fmaf(a1, inv, s0.y);
        float o2 = fmaf(a2, inv, s0.z), o3 = fmaf(a3, inv, s0.w);
        float o4 = fmaf(a4, inv, s1.x), o5 = fmaf(a5, inv, s1.y);
        float o6 = fmaf(a6, inv, s1.z), o7 = fmaf(a7, inv, s1.w);
        if (RELU) {
            o0 = fmaxf(o0, 0.f); o1 = fmaxf(o1, 0.f); o2 = fmaxf(o2, 0.f); o3 = fmaxf(o3, 0.f);
            o4 = fmaxf(o4, 0.f); o5 = fmaxf(o5, 0.f); o6 = fmaxf(o6, 0.f); o7 = fmaxf(o7, 0.f);
        }
        if (H16OUT) {
            uint4 wv;
            *(__half2*)&wv.x = __floats2half2_rn(o0, o1);
            *(__half2*)&wv.y = __floats2half2_rn(o2, o3);
            *(__half2*)&wv.z = __floats2half2_rn(o4, o5);
            *(__half2*)&wv.w = __floats2half2_rn(o6, o7);
            *(uint4*)(hout16 + base) = wv;
        } else {
            *(float4*)&h[base]     = make_float4(o0, o1, o2, o3);
            *(float4*)&h[base + 4] = make_float4(o4, o5, o6, o7);
        }
    }
}

// combined both-sides aggregation: warps [0,NP) -> p-side, [NP,NP+NU) -> u-side
template <bool RELU, bool H16OUT>
__global__ __launch_bounds__(256) void k_agg_both(
    const __half* __restrict__ t_p, const int* __restrict__ csr_p,
    const int* __restrict__ off_p, const int* __restrict__ deg_p,
    float* __restrict__ h_p, __half* __restrict__ h16_p,
    const __half* __restrict__ t_u, const int* __restrict__ csr_u,
    const int* __restrict__ off_u, const int* __restrict__ deg_u,
    float* __restrict__ h_u, __half* __restrict__ h16_u) {
    int gw = (blockIdx.x * blockDim.x + threadIdx.x) >> 5;
    int lane = threadIdx.x & 31;
    if (gw < NP) {
        agg_node<RELU, H16OUT>(t_p, csr_p, off_p, deg_p, h_p, h16_p, gw, lane);
    } else if (gw < NP + NU) {
        agg_node<RELU, H16OUT>(t_u, csr_u, off_u, deg_u, h_u, h16_u, gw - NP, lane);
    }
}

// ---------------- classifier: 16 threads per label edge, fp16 rows ----------------
__global__ __launch_bounds__(256) void k_classify(const int* __restrict__ lu,
                                                  const int* __restrict__ lp,
                                                  const __half* __restrict__ cu,
                                                  const __half* __restrict__ cp,
                                                  float* __restrict__ out) {
    int gid = blockIdx.x * blockDim.x + threadIdx.x;
    int e = gid >> 4;
    int l = gid & 15;
    if (e >= NLAB) return;
    int u = __ldg(&lu[e]);
    int p = __ldg(&lp[e]);
    uint2 ra = *(const uint2*)(cu + (size_t)u * 64 + l * 4);
    uint2 rb = *(const uint2*)(cp + (size_t)p * 64 + l * 4);
    float2 a0 = __half22float2(*(const __half2*)&ra.x);
    float2 a1 = __half22float2(*(const __half2*)&ra.y);
    float2 b0 = __half22float2(*(const __half2*)&rb.x);
    float2 b1 = __half22float2(*(const __half2*)&rb.y);
    float s = a0.x * b0.x + a0.y * b0.y + a1.x * b1.x + a1.y * b1.y;
    s += __shfl_xor_sync(0xffffffffu, s, 8);
    s += __shfl_xor_sync(0xffffffffu, s, 4);
    s += __shfl_xor_sync(0xffffffffu, s, 2);
    s += __shfl_xor_sync(0xffffffffu, s, 1);
    if (l == 0) out[e] = s;
}

// ---------------- launcher ----------------
extern "C" void kernel_launch(void* const* d_in, const int* in_sizes, int n_in,
                              void* d_out, int out_size) {
    const float* x_user    = (const float*)d_in[0];
    const float* x_product = (const float*)d_in[1];
    const float* W1_buys_l = (const float*)d_in[2];
    const float* b1_buys   = (const float*)d_in[3];
    const float* W1_buys_r = (const float*)d_in[4];
    const float* W1_rev_l  = (const float*)d_in[5];
    const float* b1_rev    = (const float*)d_in[6];
    const float* W1_rev_r  = (const float*)d_in[7];
    const float* W2_buys_l = (const float*)d_in[8];
    const float* b2_buys   = (const float*)d_in[9];
    const float* W2_buys_r = (const float*)d_in[10];
    const float* W2_rev_l  = (const float*)d_in[11];
    const float* b2_rev    = (const float*)d_in[12];
    const float* W2_rev_r  = (const float*)d_in[13];
    const int* edge_src = (const int*)d_in[14];
    const int* edge_dst = (const int*)d_in[15];
    const int* lab_u    = (const int*)d_in[16];
    const int* lab_p    = (const int*)d_in[17];
    float* out = (float*)d_out;

    static int init_done = 0;
    static int *deg_p, *deg_u, *off_p, *off_u, *cur_p, *cur_u;
    static int *csr_src, *csr_dst, *bsum_p, *bsum_u;
    static __half *tu, *tp, *tu2, *tp2, *cu, *cp;
    static float *hu, *hp, *hu2, *hp2;
    static cudaStream_t s1, s2;
    static cudaEvent_t ev[6];
    if (!init_done) {
        void* p;
        cudaGetSymbolAddress(&p, g_deg_p); deg_p = (int*)p;
        cudaGetSymbolAddress(&p, g_deg_u); deg_u = (int*)p;
        cudaGetSymbolAddress(&p, g_off_p); off_p = (int*)p;
        cudaGetSymbolAddress(&p, g_off_u); off_u = (int*)p;
        cudaGetSymbolAddress(&p, g_cur_p); cur_p = (int*)p;
        cudaGetSymbolAddress(&p, g_cur_u); cur_u = (int*)p;
        cudaGetSymbolAddress(&p, g_csr_src); csr_src = (int*)p;
        cudaGetSymbolAddress(&p, g_csr_dst); csr_dst = (int*)p;
        cudaGetSymbolAddress(&p, g_bsum_p); bsum_p = (int*)p;
        cudaGetSymbolAddress(&p, g_bsum_u); bsum_u = (int*)p;
        cudaGetSymbolAddress(&p, g_tu);  tu  = (__half*)p;
        cudaGetSymbolAddress(&p, g_tp);  tp  = (__half*)p;
        cudaGetSymbolAddress(&p, g_tu2); tu2 = (__half*)p;
        cudaGetSymbolAddress(&p, g_tp2); tp2 = (__half*)p;
        cudaGetSymbolAddress(&p, g_cu);  cu  = (__half*)p;
        cudaGetSymbolAddress(&p, g_cp);  cp  = (__half*)p;
        cudaGetSymbolAddress(&p, g_hu);  hu  = (float*)p;
        cudaGetSymbolAddress(&p, g_hp);  hp  = (float*)p;
        cudaGetSymbolAddress(&p, g_hu2); hu2 = (float*)p;
        cudaGetSymbolAddress(&p, g_hp2); hp2 = (float*)p;
        cudaFuncSetAttribute(k_gemm2_tc<64>, cudaFuncAttributeMaxDynamicSharedMemorySize, 20480);
        cudaFuncSetAttribute(k_gemm2_tc<128>, cudaFuncAttributeMaxDynamicSharedMemorySize, 40960);
        cudaStreamCreateWithFlags(&s1, cudaStreamNonBlocking);
        cudaStreamCreateWithFlags(&s2, cudaStreamNonBlocking);
        for (int i = 0; i < 6; i++) cudaEventCreateWithFlags(&ev[i], cudaEventDisableTiming);
        init_done = 1;
    }

    const int nb_p = (NP + 1023) / 1024;
    const int nb_u = (NU + 1023) / 1024;
    cudaStream_t s0 = 0;
    const int AGG_BLOCKS = ((NP + NU) * 32 + 255) / 256;

    // ---- fork: CSR chains on s1/s2 ----
    cudaEventRecord(ev[0], s0);
    cudaStreamWaitEvent(s1, ev[0], 0);
    cudaStreamWaitEvent(s2, ev[0], 0);

    k_zero_side<<<(NP + 255) / 256, 256, 0, s1>>>(deg_p, cur_p, NP);
    k_degree_side<<<(NE + 255) / 256, 256, 0, s1>>>(edge_dst, deg_p);
    k_scan1<<<nb_p, 1024, 0, s1>>>(deg_p, NP, off_p, bsum_p);
    k_scan2<<<1, 1024, 0, s1>>>(bsum_p, nb_p);
    k_scan3<<<nb_p, 1024, 0, s1>>>(off_p, NP, bsum_p);
    k_fill_side<<<(NE + 255) / 256, 256, 0, s1>>>(edge_dst, edge_src, off_p, cur_p, csr_src);

    k_zero_side<<<(NU + 255) / 256, 256, 0, s2>>>(deg_u, cur_u, NU);
    k_degree_side<<<(NE + 255) / 256, 256, 0, s2>>>(edge_src, deg_u);
    k_scan1<<<nb_u, 1024, 0, s2>>>(deg_u, NU, off_u, bsum_u);
    k_scan2<<<1, 1024, 0, s2>>>(bsum_u, nb_u);
    k_scan3<<<nb_u, 1024, 0, s2>>>(off_u, NU, bsum_u);
    k_fill_side<<<(NE + 255) / 256, 256, 0, s2>>>(edge_src, edge_dst, off_u, cur_u, csr_dst);

    // s0: layer-1 tensor-core GEMMs (overlap with CSR)
    k_gemm2_tc<64><<<(NU + 31) / 32, 256, 20480, s0>>>(x_user, W1_buys_l, W1_rev_r, b1_rev, tu, hu, NU);
    k_gemm2_tc<128><<<(NP + 31) / 32, 256, 40960, s0>>>(x_product, W1_rev_l, W1_buys_r, b1_buys, tp, hp, NP);

    // ---- join CSR into s0; everything below on one stream ----
    cudaEventRecord(ev[1], s1);
    cudaEventRecord(ev[2], s2);
    cudaStreamWaitEvent(s0, ev[1], 0);
    cudaStreamWaitEvent(s0, ev[2], 0);

    // layer-1 aggregation (both sides, one launch)
    k_agg_both<true, false><<<AGG_BLOCKS, 256, 0, s0>>>(
        tu, csr_src, off_p, deg_p, hp, (__half*)0,
        tp, csr_dst, off_u, deg_u, hu, (__half*)0);

    // layer-2 GEMMs
    k_gemm2_tc<64><<<(NP + 31) / 32, 256, 20480, s0>>>(hp, W2_rev_l, W2_buys_r, b2_buys, tp2, hp2, NP);
    k_gemm2_tc<64><<<(NU + 31) / 32, 256, 20480, s0>>>(hu, W2_buys_l, W2_rev_r, b2_rev, tu2, hu2, NU);

    // layer-2 aggregation -> fp16 classifier rows (both sides, one launch)
    k_agg_both<false, true><<<AGG_BLOCKS, 256, 0, s0>>>(
        tu2, csr_src, off_p, deg_p, hp2, cp,
        tp2, csr_dst, off_u, deg_u, hu2, cu);

    // classifier
    k_classify<<<(NLAB * 16 + 255) / 256, 256, 0, s0>>>(lab_u, lab_p, cu, cp, out);
}

// round 17
// speedup vs baseline: 1.9321x; 1.9321x over previous
#include <cuda_runtime.h>
#include <cuda_fp16.h>
#include <mma.h>

using namespace nvcuda;

#define NU 100000
#define NP 50000
#define NPP 50016          // NP padded to 32-row multiple (tail wmma stores)
#define NE 2000000
#define NLAB 500000
#define HD 64

// ---------------- device scratch ----------------
__device__ int g_deg_p[NP];
__device__ int g_deg_u[NU];
__device__ int g_off_p[NP];
__device__ int g_off_u[NU];
__device__ int g_cur_p[NP];
__device__ int g_cur_u[NU];
__device__ __align__(16) int g_csr_src[NE];
__device__ __align__(16) int g_csr_dst[NE];
__device__ __align__(16) __half g_w16[40960];        // packed fp16 weights
__device__ __align__(16) __half g_xu16[NU * 64];     // fp16 x_user
__device__ __align__(16) __half g_xp16[NPP * 128];   // fp16 x_product (padded)
__device__ __align__(16) __half g_tu[NU * HD];       // L1 messages
__device__ __align__(16) __half g_tp[NPP * HD];
__device__ __align__(16) __half g_su[NU * HD];       // L1 self terms
__device__ __align__(16) __half g_sp[NPP * HD];
__device__ __align__(16) __half g_hu16[NU * HD];     // L1 embeddings
__device__ __align__(16) __half g_hp16[NPP * HD];
__device__ __align__(16) __half g_tu2[NU * HD];      // L2 messages
__device__ __align__(16) __half g_tp2[NPP * HD];
__device__ __align__(16) __half g_su2[NU * HD];      // L2 self terms
__device__ __align__(16) __half g_sp2[NPP * HD];
__device__ __align__(16) __half g_cu[NU * HD];       // final embeddings
__device__ __align__(16) __half g_cp[NPP * HD];
__device__ int g_bsum_p[128];
__device__ int g_bsum_u[128];

// weight pack offsets
#define OFF_W1BL 0
#define OFF_W1RR 4096
#define OFF_W1RL 8192
#define OFF_W1BR 16384
#define OFF_W2BL 24576
#define OFF_W2RR 28672
#define OFF_W2RL 32768
#define OFF_W2BR 36864

// ---------------- CSR build ----------------
__global__ void k_zero_side(int* __restrict__ deg, int* __restrict__ cur, int n) {
    int i = blockIdx.x * blockDim.x + threadIdx.x;
    if (i < n) { deg[i] = 0; cur[i] = 0; }
}

__global__ void k_degree_side(const int* __restrict__ key, int* __restrict__ deg) {
    int i = blockIdx.x * blockDim.x + threadIdx.x;
    if (i < NE) atomicAdd(&deg[key[i]], 1);
}

__global__ void k_scan1(const int* __restrict__ deg, int n, int* __restrict__ out, int* __restrict__ bsums) {
    __shared__ int s[1024];
    int tid = threadIdx.x;
    int i = blockIdx.x * 1024 + tid;
    int v = (i < n) ? deg[i] : 0;
    s[tid] = v;
    __syncthreads();
    #pragma unroll
    for (int o = 1; o < 1024; o <<= 1) {
        int t = 0;
        if (tid >= o) t = s[tid - o];
        __syncthreads();
        s[tid] += t;
        __syncthreads();
    }
    if (i < n) out[i] = s[tid] - v;
    if (tid == 1023) bsums[blockIdx.x] = s[1023];
}

__global__ void k_scan2(int* __restrict__ bsums, int nb) {
    __shared__ int s[1024];
    int tid = threadIdx.x;
    int v = (tid < nb) ? bsums[tid] : 0;
    s[tid] = v;
    __syncthreads();
    #pragma unroll
    for (int o = 1; o < 1024; o <<= 1) {
        int t = 0;
        if (tid >= o) t = s[tid - o];
        __syncthreads();
        s[tid] += t;
        __syncthreads();
    }
    if (tid < nb) bsums[tid] = s[tid] - v;
}

__global__ void k_scan3(int* __restrict__ out, int n, const int* __restrict__ bsums) {
    int i = blockIdx.x * 1024 + threadIdx.x;
    if (i < n) out[i] += bsums[blockIdx.x];
}

__global__ void k_fill_side(const int* __restrict__ key, const int* __restrict__ val,
                            const int* __restrict__ off, int* __restrict__ cur,
                            int* __restrict__ csr) {
    int i = blockIdx.x * blockDim.x + threadIdx.x;
    if (i < NE) {
        int k = key[i];
        int slot = atomicAdd(&cur[k], 1);
        csr[off[k] + slot] = val[i];
    }
}

// ---------------- conversions ----------------
__global__ void k_convW(const float* p0, const float* p1, const float* p2, const float* p3,
                        const float* p4, const float* p5, const float* p6, const float* p7,
                        __half* __restrict__ dst) {
    int i = blockIdx.x * blockDim.x + threadIdx.x;
    if (i >= 40960) return;
    float v;
    if (i < 4096)        v = p0[i];
    else if (i < 8192)   v = p1[i - 4096];
    else if (i < 16384)  v = p2[i - 8192];
    else if (i < 24576)  v = p3[i - 16384];
    else if (i < 28672)  v = p4[i - 24576];
    else if (i < 32768)  v = p5[i - 28672];
    else if (i < 36864)  v = p6[i - 32768];
    else                 v = p7[i - 36864];
    dst[i] = __float2half_rn(v);
}

__global__ void k_convX(const float* __restrict__ src, __half* __restrict__ dst,
                        int nsrc, int ntot) {
    int i = blockIdx.x * blockDim.x + threadIdx.x;
    for (; i < ntot; i += gridDim.x * blockDim.x)
        dst[i] = __float2half_rn(i < nsrc ? src[i] : 0.f);
}

// ---------------- tensor-core dual GEMM: outa = x@Wa, outb = x@Wb (both fp16) ----------------
// 32 rows/block, 8 warps -> 2x4 wmma tiles; A/W already fp16 in global.
template <int DIN>
__global__ __launch_bounds__(256) void k_gemm2_tc(const __half* __restrict__ x16,
                                                  const __half* __restrict__ Wa16,
                                                  const __half* __restrict__ Wb16,
                                                  __half* __restrict__ outa,
                                                  __half* __restrict__ outb) {
    extern __shared__ __align__(16) __half smh[];
    __half* As = smh;                        // 32 x (DIN+8)
    __half* Wa = smh + 32 * (DIN + 8);       // DIN x 72
    __half* Wb = Wa + DIN * 72;              // DIN x 72
    int tid = threadIdx.x;
    size_t row0 = (size_t)blockIdx.x * 32;

    // stage A (uint = 2 halves)
    {
        const uint* xs = (const uint*)(x16 + row0 * DIN);
        const int HA = DIN / 2;
        for (int i = tid; i < 32 * HA; i += 256) {
            int r = i / HA, c = i % HA;
            ((uint*)As)[r * ((DIN + 8) / 2) + c] = xs[r * HA + c];
        }
    }
    // stage W (rows of 64 halves -> stride 72)
    for (int i = tid; i < DIN * 32; i += 256) {
        int k = i >> 5, c = i & 31;
        ((uint*)Wa)[k * 36 + c] = ((const uint*)Wa16)[k * 32 + c];
        ((uint*)Wb)[k * 36 + c] = ((const uint*)Wb16)[k * 32 + c];
    }
    __syncthreads();

    int w = tid >> 5;
    int rt = w >> 2, ct = w & 3;

    wmma::fragment<wmma::matrix_a, 16, 16, 16, __half, wmma::row_major> fa;
    wmma::fragment<wmma::matrix_b, 16, 16, 16, __half, wmma::row_major> fba, fbb;
    wmma::fragment<wmma::accumulator, 16, 16, 16, float> ca, cb;
    wmma::fill_fragment(ca, 0.f);
    wmma::fill_fragment(cb, 0.f);

    #pragma unroll
    for (int k = 0; k < DIN; k += 16) {
        wmma::load_matrix_sync(fa, As + (rt * 16) * (DIN + 8) + k, DIN + 8);
        wmma::load_matrix_sync(fba, Wa + k * 72 + ct * 16, 72);
        wmma::load_matrix_sync(fbb, Wb + k * 72 + ct * 16, 72);
        wmma::mma_sync(ca, fa, fba, ca);
        wmma::mma_sync(cb, fa, fbb, cb);
    }

    // epilogue via smem (32x64 f32 = 8KB, fits in staging region)
    float* outS = (float*)smh;
    __syncthreads();
    wmma::store_matrix_sync(outS + (rt * 16) * 64 + ct * 16, ca, 64, wmma::mem_row_major);
    __syncthreads();
    for (int i = tid; i < 1024; i += 256) {         // 2048 floats as float2 -> half2
        float2 v = ((const float2*)outS)[i];
        ((__half2*)(outa + row0 * 64))[i] = __floats2half2_rn(v.x, v.y);
    }
    __syncthreads();
    wmma::store_matrix_sync(outS + (rt * 16) * 64 + ct * 16, cb, 64, wmma::mem_row_major);
    __syncthreads();
    for (int i = tid; i < 1024; i += 256) {
        float2 v = ((const float2*)outS)[i];
        ((__half2*)(outb + row0 * 64))[i] = __floats2half2_rn(v.x, v.y);
    }
}

// ---------------- aggregation: warp/node, fp16 gather, self+bias in epilogue ----------------
template <bool RELU>
__global__ __launch_bounds__(256) void k_agg(const __half* __restrict__ t,
                                             const int* __restrict__ csr,
                                             const int* __restrict__ off,
                                             const int* __restrict__ deg,
                                             const __half* __restrict__ self16,
                                             const float* __restrict__ bias,
                                             __half* __restrict__ out16, int n) {
    int warp = (blockIdx.x * blockDim.x + threadIdx.x) >> 5;
    int lane = threadIdx.x & 31;
    if (warp >= n) return;
    int start = off[warp];
    int d = deg[warp];
    int half_ = lane >> 4;
    int l16 = lane & 15;

    float4 acc = make_float4(0.f, 0.f, 0.f, 0.f);
    for (int e = half_; e < d; e += 2) {
        int s = __ldg(&csr[start + e]);
        uint2 r = *(const uint2*)(t + (size_t)s * 64 + l16 * 4);
        float2 f0 = __half22float2(*(const __half2*)&r.x);
        float2 f1 = __half22float2(*(const __half2*)&r.y);
        acc.x += f0.x; acc.y += f0.y; acc.z += f1.x; acc.w += f1.y;
    }
    acc.x += __shfl_down_sync(0xffffffffu, acc.x, 16);
    acc.y += __shfl_down_sync(0xffffffffu, acc.y, 16);
    acc.z += __shfl_down_sync(0xffffffffu, acc.z, 16);
    acc.w += __shfl_down_sync(0xffffffffu, acc.w, 16);

    if (lane < 16) {
        float inv = 1.0f / (float)((d > 1) ? d : 1);
        size_t base = (size_t)warp * 64 + l16 * 4;
        uint2 sr = *(const uint2*)(self16 + base);
        float2 s0 = __half22float2(*(const __half2*)&sr.x);
        float2 s1 = __half22float2(*(const __half2*)&sr.y);
        float4 bv = *(const float4*)(bias + l16 * 4);
        float o0 = fmaf(acc.x, inv, s0.x + bv.x);
        float o1 = fmaf(acc.y, inv, s0.y + bv.y);
        float o2 = fmaf(acc.z, inv, s1.x + bv.z);
        float o3 = fmaf(acc.w, inv, s1.y + bv.w);
        if (RELU) {
            o0 = fmaxf(o0, 0.f); o1 = fmaxf(o1, 0.f);
            o2 = fmaxf(o2, 0.f); o3 = fmaxf(o3, 0.f);
        }
        uint2 wv;
        *(__half2*)&wv.x = __floats2half2_rn(o0, o1);
        *(__half2*)&wv.y = __floats2half2_rn(o2, o3);
        *(uint2*)(out16 + base) = wv;
    }
}

// ---------------- classifier: 16 threads/label edge, fp16 rows ----------------
__global__ __launch_bounds__(256) void k_classify(const int* __restrict__ lu,
                                                  const int* __restrict__ lp,
                                                  const __half* __restrict__ cu,
                                                  const __half* __restrict__ cp,
                                                  float* __restrict__ out) {
    int gid = blockIdx.x * blockDim.x + threadIdx.x;
    int e = gid >> 4;
    int l = gid & 15;
    if (e >= NLAB) return;
    int u = __ldg(&lu[e]);
    int p = __ldg(&lp[e]);
    uint2 ra = *(const uint2*)(cu + (size_t)u * 64 + l * 4);
    uint2 rb = *(const uint2*)(cp + (size_t)p * 64 + l * 4);
    float2 a0 = __half22float2(*(const __half2*)&ra.x);
    float2 a1 = __half22float2(*(const __half2*)&ra.y);
    float2 b0 = __half22float2(*(const __half2*)&rb.x);
    float2 b1 = __half22float2(*(const __half2*)&rb.y);
    float s = a0.x * b0.x + a0.y * b0.y + a1.x * b1.x + a1.y * b1.y;
    s += __shfl_xor_sync(0xffffffffu, s, 8);
    s += __shfl_xor_sync(0xffffffffu, s, 4);
    s += __shfl_xor_sync(0xffffffffu, s, 2);
    s += __shfl_xor_sync(0xffffffffu, s, 1);
    if (l == 0) out[e] = s;
}

// ---------------- launcher ----------------
extern "C" void kernel_launch(void* const* d_in, const int* in_sizes, int n_in,
                              void* d_out, int out_size) {
    const float* x_user    = (const float*)d_in[0];
    const float* x_product = (const float*)d_in[1];
    const float* W1_buys_l = (const float*)d_in[2];
    const float* b1_buys   = (const float*)d_in[3];
    const float* W1_buys_r = (const float*)d_in[4];
    const float* W1_rev_l  = (const float*)d_in[5];
    const float* b1_rev    = (const float*)d_in[6];
    const float* W1_rev_r  = (const float*)d_in[7];
    const float* W2_buys_l = (const float*)d_in[8];
    const float* b2_buys   = (const float*)d_in[9];
    const float* W2_buys_r = (const float*)d_in[10];
    const float* W2_rev_l  = (const float*)d_in[11];
    const float* b2_rev    = (const float*)d_in[12];
    const float* W2_rev_r  = (const float*)d_in[13];
    const int* edge_src = (const int*)d_in[14];
    const int* edge_dst = (const int*)d_in[15];
    const int* lab_u    = (const int*)d_in[16];
    const int* lab_p    = (const int*)d_in[17];
    float* out = (float*)d_out;

    static int init_done = 0;
    static int *deg_p, *deg_u, *off_p, *off_u, *cur_p, *cur_u;
    static int *csr_src, *csr_dst, *bsum_p, *bsum_u;
    static __half *w16, *xu16, *xp16, *tu, *tp, *su, *sp, *hu16, *hp16;
    static __half *tu2, *tp2, *su2, *sp2, *cu, *cp;
    static cudaStream_t s1, s2;
    static cudaEvent_t ev[8];
    if (!init_done) {
        void* p;
        cudaGetSymbolAddress(&p, g_deg_p); deg_p = (int*)p;
        cudaGetSymbolAddress(&p, g_deg_u); deg_u = (int*)p;
        cudaGetSymbolAddress(&p, g_off_p); off_p = (int*)p;
        cudaGetSymbolAddress(&p, g_off_u); off_u = (int*)p;
        cudaGetSymbolAddress(&p, g_cur_p); cur_p = (int*)p;
        cudaGetSymbolAddress(&p, g_cur_u); cur_u = (int*)p;
        cudaGetSymbolAddress(&p, g_csr_src); csr_src = (int*)p;
        cudaGetSymbolAddress(&p, g_csr_dst); csr_dst = (int*)p;
        cudaGetSymbolAddress(&p, g_bsum_p); bsum_p = (int*)p;
        cudaGetSymbolAddress(&p, g_bsum_u); bsum_u = (int*)p;
        cudaGetSymbolAddress(&p, g_w16);  w16  = (__half*)p;
        cudaGetSymbolAddress(&p, g_xu16); xu16 = (__half*)p;
        cudaGetSymbolAddress(&p, g_xp16); xp16 = (__half*)p;
        cudaGetSymbolAddress(&p, g_tu);  tu  = (__half*)p;
        cudaGetSymbolAddress(&p, g_tp);  tp  = (__half*)p;
        cudaGetSymbolAddress(&p, g_su);  su  = (__half*)p;
        cudaGetSymbolAddress(&p, g_sp);  sp  = (__half*)p;
        cudaGetSymbolAddress(&p, g_hu16); hu16 = (__half*)p;
        cudaGetSymbolAddress(&p, g_hp16); hp16 = (__half*)p;
        cudaGetSymbolAddress(&p, g_tu2); tu2 = (__half*)p;
        cudaGetSymbolAddress(&p, g_tp2); tp2 = (__half*)p;
        cudaGetSymbolAddress(&p, g_su2); su2 = (__half*)p;
        cudaGetSymbolAddress(&p, g_sp2); sp2 = (__half*)p;
        cudaGetSymbolAddress(&p, g_cu);  cu  = (__half*)p;
        cudaGetSymbolAddress(&p, g_cp);  cp  = (__half*)p;
        cudaStreamCreateWithFlags(&s1, cudaStreamNonBlocking);
        cudaStreamCreateWithFlags(&s2, cudaStreamNonBlocking);
        for (int i = 0; i < 8; i++) cudaEventCreateWithFlags(&ev[i], cudaEventDisableTiming);
        init_done = 1;
    }

    const int nb_p = (NP + 1023) / 1024;
    const int nb_u = (NU + 1023) / 1024;
    const int SM64 = (32 * 72 + 2 * 64 * 72) * 2;     // 23040
    const int SM128 = (32 * 136 + 2 * 128 * 72) * 2;  // 45568
    cudaStream_t s0 = 0;

    // ---- fork: CSR chains ----
    cudaEventRecord(ev[0], s0);
    cudaStreamWaitEvent(s1, ev[0], 0);
    cudaStreamWaitEvent(s2, ev[0], 0);

    k_zero_side<<<(NP + 255) / 256, 256, 0, s1>>>(deg_p, cur_p, NP);
    k_degree_side<<<(NE + 255) / 256, 256, 0, s1>>>(edge_dst, deg_p);
    k_scan1<<<nb_p, 1024, 0, s1>>>(deg_p, NP, off_p, bsum_p);
    k_scan2<<<1, 1024, 0, s1>>>(bsum_p, nb_p);
    k_scan3<<<nb_p, 1024, 0, s1>>>(off_p, NP, bsum_p);
    k_fill_side<<<(NE + 255) / 256, 256, 0, s1>>>(edge_dst, edge_src, off_p, cur_p, csr_src);

    k_zero_side<<<(NU + 255) / 256, 256, 0, s2>>>(deg_u, cur_u, NU);
    k_degree_side<<<(NE + 255) / 256, 256, 0, s2>>>(edge_src, deg_u);
    k_scan1<<<nb_u, 1024, 0, s2>>>(deg_u, NU, off_u, bsum_u);
    k_scan2<<<1, 1024, 0, s2>>>(bsum_u, nb_u);
    k_scan3<<<nb_u, 1024, 0, s2>>>(off_u, NU, bsum_u);
    k_fill_side<<<(NE + 255) / 256, 256, 0, s2>>>(edge_src, edge_dst, off_u, cur_u, csr_dst);

    // s0: conversions, then layer-1 tc GEMMs
    k_convW<<<160, 256, 0, s0>>>(W1_buys_l, W1_rev_r, W1_rev_l, W1_buys_r,
                                 W2_buys_l, W2_rev_r, W2_rev_l, W2_buys_r, w16);
    k_convX<<<512, 256, 0, s0>>>(x_user, xu16, NU * 64, NU * 64);
    k_convX<<<512, 256, 0, s0>>>(x_product, xp16, NP * 128, NPP * 128);
    k_gemm2_tc<64><<<NU / 32, 256, SM64, s0>>>(xu16, w16 + OFF_W1BL, w16 + OFF_W1RR, tu, su);
    k_gemm2_tc<128><<<NPP / 32, 256, SM128, s0>>>(xp16, w16 + OFF_W1RL, w16 + OFF_W1BR, tp, sp);
    cudaEventRecord(ev[1], s0);

    // layer-1 aggregation + layer-2 GEMMs per side
    cudaStreamWaitEvent(s1, ev[1], 0);
    cudaStreamWaitEvent(s2, ev[1], 0);
    k_agg<true><<<(NP * 32 + 255) / 256, 256, 0, s1>>>(tu, csr_src, off_p, deg_p, sp, b1_buys, hp16, NP);
    k_gemm2_tc<64><<<NPP / 32, 256, SM64, s1>>>(hp16, w16 + OFF_W2RL, w16 + OFF_W2BR, tp2, sp2);
    cudaEventRecord(ev[2], s1);   // tp2, sp2 ready

    k_agg<true><<<(NU * 32 + 255) / 256, 256, 0, s2>>>(tp, csr_dst, off_u, deg_u, su, b1_rev, hu16, NU);
    k_gemm2_tc<64><<<NU / 32, 256, SM64, s2>>>(hu16, w16 + OFF_W2BL, w16 + OFF_W2RR, tu2, su2);
    cudaEventRecord(ev[3], s2);   // tu2, su2 ready

    // layer-2 aggregation (cross deps)
    cudaStreamWaitEvent(s1, ev[3], 0);
    cudaStreamWaitEvent(s2, ev[2], 0);
    k_agg<false><<<(NP * 32 + 255) / 256, 256, 0, s1>>>(tu2, csr_src, off_p, deg_p, sp2, b2_buys, cp, NP);
    k_agg<false><<<(NU * 32 + 255) / 256, 256, 0, s2>>>(tp2, csr_dst, off_u, deg_u, su2, b2_rev, cu, NU);

    // ---- join, classify ----
    cudaEventRecord(ev[4], s1);
    cudaEventRecord(ev[5], s2);
    cudaStreamWaitEvent(s0, ev[4], 0);
    cudaStreamWaitEvent(s0, ev[5], 0);
    k_classify<<<(NLAB * 16 + 255) / 256, 256, 0, s0>>>(lab_u, lab_p, cu, cp, out);
}